// round 2
// baseline (speedup 1.0000x reference)
#include <cuda_runtime.h>

#define BB 32
#define TT 8192
#define HH 256
#define CHUNK 256
#define NCHUNK (TT / CHUNK)   // 32

// Scratch (allocation-free rule: __device__ globals)
__device__ float g_v[BB * HH];              // v[b,h] = sum_o W1[o,h] * h_t[b,o]
__device__ float g_scores[BB * TT];         // raw logits
__device__ float g_pm[BB * NCHUNK];         // per-chunk running max
__device__ float g_pl[BB * NCHUNK];         // per-chunk sum exp
__device__ float g_pc[BB * NCHUNK * HH];    // per-chunk partial context (unnormalized)

// ---------------------------------------------------------------------------
// Kernel 0: v[b,h] = sum_o W1[o,h] * hs[b, T-1, o]
// ---------------------------------------------------------------------------
__global__ void compute_v_kernel(const float* __restrict__ hs,
                                 const float* __restrict__ W1) {
    int b = blockIdx.x;
    int h = threadIdx.x;  // 256 threads
    __shared__ float ht[HH];
    ht[h] = hs[(size_t)b * TT * HH + (size_t)(TT - 1) * HH + h];
    __syncthreads();
    float acc = 0.f;
#pragma unroll 8
    for (int o = 0; o < HH; o++) {
        acc += W1[o * HH + h] * ht[o];  // coalesced across h
    }
    g_v[b * HH + h] = acc;
}

// ---------------------------------------------------------------------------
// Kernel 1: fused score + online-softmax + partial context over a T-chunk.
// grid = (NCHUNK, B), block = 256 threads = 8 warps. Each warp streams rows
// t = warp, warp+8, ... within the chunk. Single pass over hidden_states.
// ---------------------------------------------------------------------------
__global__ void __launch_bounds__(256) pass1_kernel(const float* __restrict__ hs) {
    const int chunk = blockIdx.x;
    const int b = blockIdx.y;
    const int tid = threadIdx.x;
    const int w = tid >> 5;
    const int lane = tid & 31;

    // per-lane slice of v: h = lane*4..+3 and 128+lane*4..+3
    const float4* v4 = (const float4*)(g_v + b * HH);
    const float4 va = v4[lane];
    const float4 vb = v4[32 + lane];

    const float4* x4 =
        (const float4*)(hs + (size_t)b * TT * HH + (size_t)chunk * CHUNK * HH);

    float m = -1e30f;
    float l = 0.f;
    float4 ca = make_float4(0.f, 0.f, 0.f, 0.f);
    float4 cb = make_float4(0.f, 0.f, 0.f, 0.f);

    for (int r = w; r < CHUNK; r += 8) {
        const float4* row = x4 + (size_t)r * (HH / 4);
        float4 x1 = row[lane];
        float4 x2 = row[32 + lane];

        float s = x1.x * va.x + x1.y * va.y + x1.z * va.z + x1.w * va.w
                + x2.x * vb.x + x2.y * vb.y + x2.z * vb.z + x2.w * vb.w;
#pragma unroll
        for (int off = 16; off; off >>= 1)
            s += __shfl_xor_sync(0xffffffffu, s, off);
        // all lanes now hold the full row score
        if (lane == 0) g_scores[b * TT + chunk * CHUNK + r] = s;

        float mn = fmaxf(m, s);
        float corr = __expf(m - mn);   // 0 on first iter (m=-1e30)
        float p = __expf(s - mn);
        l = l * corr + p;
        ca.x = ca.x * corr + p * x1.x;
        ca.y = ca.y * corr + p * x1.y;
        ca.z = ca.z * corr + p * x1.z;
        ca.w = ca.w * corr + p * x1.w;
        cb.x = cb.x * corr + p * x2.x;
        cb.y = cb.y * corr + p * x2.y;
        cb.z = cb.z * corr + p * x2.z;
        cb.w = cb.w * corr + p * x2.w;
        m = mn;
    }

    // combine the 8 warps' partials within the CTA
    __shared__ float s_m[8];
    __shared__ float s_l[8];
    __shared__ float s_c[8][HH];
    if (lane == 0) { s_m[w] = m; s_l[w] = l; }
    s_c[w][lane * 4 + 0] = ca.x;
    s_c[w][lane * 4 + 1] = ca.y;
    s_c[w][lane * 4 + 2] = ca.z;
    s_c[w][lane * 4 + 3] = ca.w;
    s_c[w][128 + lane * 4 + 0] = cb.x;
    s_c[w][128 + lane * 4 + 1] = cb.y;
    s_c[w][128 + lane * 4 + 2] = cb.z;
    s_c[w][128 + lane * 4 + 3] = cb.w;
    __syncthreads();

    float M = -1e30f;
#pragma unroll
    for (int ww = 0; ww < 8; ww++) M = fmaxf(M, s_m[ww]);
    float L = 0.f, C = 0.f;
#pragma unroll
    for (int ww = 0; ww < 8; ww++) {
        float e = __expf(s_m[ww] - M);
        L += s_l[ww] * e;
        C += s_c[ww][tid] * e;
    }
    int pidx = b * NCHUNK + chunk;
    g_pc[pidx * HH + tid] = C;
    if (tid == 0) { g_pm[pidx] = M; g_pl[pidx] = L; }
}

// ---------------------------------------------------------------------------
// Kernel 2: per batch — merge chunk partials, write attention_weights,
// compute attention_vector = tanh([context, h_t] @ W2^T).
// grid = B, block = 256 threads.
// Output layout: [attention_vector (B*H) | attention_weights (B*T)]
// ---------------------------------------------------------------------------
__global__ void __launch_bounds__(256) pass2_kernel(const float* __restrict__ hs,
                                                    const float* __restrict__ W2,
                                                    float* __restrict__ out) {
    const int b = blockIdx.x;
    const int tid = threadIdx.x;

    __shared__ float ctx[HH];
    __shared__ float ht[HH];

    // global max / sum (redundant per-thread, tiny)
    float M = -1e30f;
#pragma unroll 8
    for (int i = 0; i < NCHUNK; i++) M = fmaxf(M, g_pm[b * NCHUNK + i]);
    float L = 0.f, C = 0.f;
#pragma unroll 4
    for (int i = 0; i < NCHUNK; i++) {
        float e = __expf(g_pm[b * NCHUNK + i] - M);
        L += g_pl[b * NCHUNK + i] * e;
        C += g_pc[(b * NCHUNK + i) * HH + tid] * e;  // coalesced across tid
    }
    const float invL = 1.f / L;
    // FIX (R1): context must be normalized by L before feeding the tanh head.
    ctx[tid] = C * invL;
    ht[tid] = hs[(size_t)b * TT * HH + (size_t)(TT - 1) * HH + tid];
    __syncthreads();

    float* out_av = out;              // B*H
    float* out_w = out + BB * HH;     // B*T

    // attention_weights
#pragma unroll 4
    for (int t = tid; t < TT; t += 256)
        out_w[b * TT + t] = __expf(g_scores[b * TT + t] - M) * invL;

    // attention_vector: av[b,o] = tanh( sum_j ctx[j]*W2[o,j] + sum_j ht[j]*W2[o,256+j] )
    const float* w2row = W2 + (size_t)tid * 2 * HH;  // row o = tid
    float acc = 0.f;
#pragma unroll 8
    for (int j = 0; j < HH; j++) acc += ctx[j] * w2row[j];
#pragma unroll 8
    for (int j = 0; j < HH; j++) acc += ht[j] * w2row[HH + j];
    out_av[b * HH + tid] = tanhf(acc);
}

// ---------------------------------------------------------------------------
extern "C" void kernel_launch(void* const* d_in, const int* in_sizes, int n_in,
                              void* d_out, int out_size) {
    const float* hs = (const float*)d_in[0];   // (32, 8192, 256) f32
    const float* W1 = (const float*)d_in[1];   // (256, 256) f32
    const float* W2 = (const float*)d_in[2];   // (256, 512) f32
    float* out = (float*)d_out;

    compute_v_kernel<<<BB, HH>>>(hs, W1);
    pass1_kernel<<<dim3(NCHUNK, BB), 256>>>(hs);
    pass2_kernel<<<BB, HH>>>(hs, W2, out);
}

// round 3
// speedup vs baseline: 1.6445x; 1.6445x over previous
#include <cuda_runtime.h>
#include <cstdint>

#define BB 32
#define TT 8192
#define HH 256
#define CHUNK 128
#define NCH (TT / CHUNK)          // 64 chunks per batch
#define NSTAGE 2
#define SROWS 16
#define NSTG (CHUNK / SROWS)      // 8 stages per CTA
#define SBYTES (SROWS * HH * 4)   // 16 KB per stage

// Scratch (__device__ globals: allocation-free rule)
__device__ float g_vp[BB * 8 * HH];       // split-K partials of v
__device__ float g_v[BB * HH];            // v[b,h] = sum_o W1[o,h] * h_t[b,o]
__device__ float g_scores[BB * TT];       // raw logits
__device__ float g_pm[BB * NCH];          // per-chunk max
__device__ float g_pl[BB * NCH];          // per-chunk sum-exp
__device__ float g_pc[BB * NCH * HH];     // per-chunk partial context
__device__ float g_M[BB];
__device__ float g_invL[BB];

// ---------------- mbarrier / bulk-async helpers ----------------
__device__ __forceinline__ uint32_t smem_u32(const void* p) {
    return (uint32_t)__cvta_generic_to_shared(p);
}
__device__ __forceinline__ void mbar_init(uint32_t a, uint32_t cnt) {
    asm volatile("mbarrier.init.shared.b64 [%0], %1;" :: "r"(a), "r"(cnt) : "memory");
}
__device__ __forceinline__ void mbar_expect_tx(uint32_t a, uint32_t bytes) {
    asm volatile("mbarrier.arrive.expect_tx.shared.b64 _, [%0], %1;"
                 :: "r"(a), "r"(bytes) : "memory");
}
__device__ __forceinline__ void mbar_arrive(uint32_t a) {
    asm volatile("mbarrier.arrive.shared.b64 _, [%0];" :: "r"(a) : "memory");
}
__device__ __forceinline__ void mbar_wait(uint32_t a, uint32_t parity) {
    asm volatile(
        "{\n\t.reg .pred P;\n\t"
        "LAB_%=:\n\t"
        "mbarrier.try_wait.parity.shared.b64 P, [%0], %1;\n\t"
        "@P bra.uni DONE_%=;\n\t"
        "bra.uni LAB_%=;\n\t"
        "DONE_%=:\n\t}"
        :: "r"(a), "r"(parity) : "memory");
}
__device__ __forceinline__ void bulk_g2s(uint32_t dst, const void* src,
                                         uint32_t bytes, uint32_t mbar) {
    asm volatile(
        "cp.async.bulk.shared::cluster.global.mbarrier::complete_tx::bytes "
        "[%0], [%1], %2, [%3];"
        :: "r"(dst), "l"(src), "r"(bytes), "r"(mbar) : "memory");
}

// ---------------------------------------------------------------------------
// Kernel 0a: split-K partial of v.  grid=(BB, 8), block=256.
// vp[b,s,h] = sum_{o in [32s,32s+32)} W1[o,h] * h_t[b,o]
// ---------------------------------------------------------------------------
__global__ void __launch_bounds__(256) vpart_kernel(const float* __restrict__ hs,
                                                    const float* __restrict__ W1) {
    const int b = blockIdx.x;
    const int s = blockIdx.y;
    const int h = threadIdx.x;
    __shared__ float ht[32];
    if (h < 32)
        ht[h] = hs[(size_t)b * TT * HH + (size_t)(TT - 1) * HH + s * 32 + h];
    __syncthreads();
    float acc = 0.f;
#pragma unroll
    for (int o = 0; o < 32; o++)
        acc += W1[(s * 32 + o) * HH + h] * ht[o];   // 32 independent coalesced LDGs
    g_vp[(b * 8 + s) * HH + h] = acc;
}

// Kernel 0b: reduce partials.  grid=BB, block=256.
__global__ void __launch_bounds__(256) vreduce_kernel() {
    const int b = blockIdx.x;
    const int h = threadIdx.x;
    float a = 0.f;
#pragma unroll
    for (int s = 0; s < 8; s++) a += g_vp[(b * 8 + s) * HH + h];
    g_v[b * HH + h] = a;
}

// ---------------------------------------------------------------------------
// Kernel 1: bulk-async-staged fused score + online softmax + partial context.
// grid=(NCH, BB)=2048 CTAs, block=256 (8 warps). Each CTA streams its 128-row
// (128 KB) chunk through a 2-stage 16 KB smem ring; warp w consumes rows
// {2w, 2w+1} of each stage.
// ---------------------------------------------------------------------------
__global__ void __launch_bounds__(256) pass1_kernel(const float* __restrict__ hs) {
    __shared__ __align__(16) float buf[NSTAGE][SROWS * HH];      // 32 KB
    __shared__ __align__(8) unsigned long long mb_full[NSTAGE];
    __shared__ __align__(8) unsigned long long mb_empty[NSTAGE];
    __shared__ float s_m[8], s_l[8];
    __shared__ float s_c[8][HH];                                  // 8 KB

    const int chunk = blockIdx.x;
    const int b = blockIdx.y;
    const int tid = threadIdx.x;
    const int w = tid >> 5;
    const int lane = tid & 31;

    uint32_t full_a[NSTAGE], empty_a[NSTAGE], buf_a[NSTAGE];
#pragma unroll
    for (int i = 0; i < NSTAGE; i++) {
        full_a[i] = smem_u32(&mb_full[i]);
        empty_a[i] = smem_u32(&mb_empty[i]);
        buf_a[i] = smem_u32(&buf[i][0]);
    }

    if (tid == 0) {
#pragma unroll
        for (int i = 0; i < NSTAGE; i++) {
            mbar_init(full_a[i], 1);
            mbar_init(empty_a[i], 8);    // one arrive per warp
        }
    }
    __syncthreads();

    // per-lane slice of v: h = lane*4..+3 and 128+lane*4..+3
    const float4* v4 = (const float4*)(g_v + b * HH);
    const float4 va = v4[lane];
    const float4 vb = v4[32 + lane];

    const char* src =
        (const char*)(hs + ((size_t)b * TT + (size_t)chunk * CHUNK) * HH);

    // prime the pipeline
    if (tid == 0) {
#pragma unroll
        for (int i = 0; i < NSTAGE; i++) {
            mbar_expect_tx(full_a[i], SBYTES);
            bulk_g2s(buf_a[i], src + (size_t)i * SBYTES, SBYTES, full_a[i]);
        }
    }

    float m = -1e30f, l = 0.f;
    float4 ca = make_float4(0.f, 0.f, 0.f, 0.f);
    float4 cb = make_float4(0.f, 0.f, 0.f, 0.f);
    float* scores = g_scores + b * TT + chunk * CHUNK;

    for (int s = 0; s < NSTG; s++) {
        const int slot = s & (NSTAGE - 1);
        mbar_wait(full_a[slot], (s / NSTAGE) & 1);

        const float4* bf = (const float4*)buf[slot];
#pragma unroll
        for (int rr = 0; rr < 2; rr++) {
            const int r = w * 2 + rr;
            float4 x1 = bf[r * 64 + lane];
            float4 x2 = bf[r * 64 + 32 + lane];
            float sc = x1.x * va.x + x1.y * va.y + x1.z * va.z + x1.w * va.w
                     + x2.x * vb.x + x2.y * vb.y + x2.z * vb.z + x2.w * vb.w;
#pragma unroll
            for (int off = 16; off; off >>= 1)
                sc += __shfl_xor_sync(0xffffffffu, sc, off);
            if (lane == 0) scores[s * SROWS + r] = sc;

            float mn = fmaxf(m, sc);
            float corr = __expf(m - mn);   // 0 on first row
            float p = __expf(sc - mn);
            l = l * corr + p;
            ca.x = ca.x * corr + p * x1.x;
            ca.y = ca.y * corr + p * x1.y;
            ca.z = ca.z * corr + p * x1.z;
            ca.w = ca.w * corr + p * x1.w;
            cb.x = cb.x * corr + p * x2.x;
            cb.y = cb.y * corr + p * x2.y;
            cb.z = cb.z * corr + p * x2.z;
            cb.w = cb.w * corr + p * x2.w;
            m = mn;
        }

        if (lane == 0) mbar_arrive(empty_a[slot]);   // warp done with this stage

        if (tid == 0 && s + NSTAGE < NSTG) {
            const int ns = s + NSTAGE;               // same slot as `slot`
            mbar_wait(empty_a[slot], ((ns / NSTAGE) - 1) & 1);
            mbar_expect_tx(full_a[slot], SBYTES);
            bulk_g2s(buf_a[slot], src + (size_t)ns * SBYTES, SBYTES, full_a[slot]);
        }
    }

    // combine the 8 warps' partials
    if (lane == 0) { s_m[w] = m; s_l[w] = l; }
    s_c[w][lane * 4 + 0] = ca.x;
    s_c[w][lane * 4 + 1] = ca.y;
    s_c[w][lane * 4 + 2] = ca.z;
    s_c[w][lane * 4 + 3] = ca.w;
    s_c[w][128 + lane * 4 + 0] = cb.x;
    s_c[w][128 + lane * 4 + 1] = cb.y;
    s_c[w][128 + lane * 4 + 2] = cb.z;
    s_c[w][128 + lane * 4 + 3] = cb.w;
    __syncthreads();

    float M = -1e30f;
#pragma unroll
    for (int ww = 0; ww < 8; ww++) M = fmaxf(M, s_m[ww]);
    float L = 0.f, C = 0.f;
#pragma unroll
    for (int ww = 0; ww < 8; ww++) {
        float e = __expf(s_m[ww] - M);
        L += s_l[ww] * e;
        C += s_c[ww][tid] * e;
    }
    const int pidx = b * NCH + chunk;
    g_pc[pidx * HH + tid] = C;
    if (tid == 0) { g_pm[pidx] = M; g_pl[pidx] = L; }
}

// ---------------------------------------------------------------------------
// Kernel 2: merge chunk partials + tanh head.  grid=BB, block=256.
// ---------------------------------------------------------------------------
__global__ void __launch_bounds__(256) merge_kernel(const float* __restrict__ hs,
                                                    const float* __restrict__ W2,
                                                    float* __restrict__ out) {
    const int b = blockIdx.x;
    const int tid = threadIdx.x;
    __shared__ float ctx[HH];
    __shared__ float ht[HH];

    float M = -1e30f;
#pragma unroll 8
    for (int i = 0; i < NCH; i++) M = fmaxf(M, g_pm[b * NCH + i]);
    float L = 0.f, C = 0.f;
#pragma unroll 4
    for (int i = 0; i < NCH; i++) {
        float e = __expf(g_pm[b * NCH + i] - M);
        L += g_pl[b * NCH + i] * e;
        C += g_pc[(b * NCH + i) * HH + tid] * e;
    }
    const float invL = 1.f / L;
    ctx[tid] = C * invL;                                   // normalized context
    ht[tid] = hs[(size_t)b * TT * HH + (size_t)(TT - 1) * HH + tid];
    if (tid == 0) { g_M[b] = M; g_invL[b] = invL; }
    __syncthreads();

    // attention_vector[b,o] = tanh( [ctx, ht] . W2[o,:] ), o = tid
    const float4* w2r = (const float4*)(W2 + (size_t)tid * 2 * HH);
    float acc = 0.f;
#pragma unroll 8
    for (int j = 0; j < 64; j++) {
        float4 a = w2r[j];
        acc += a.x * ctx[j * 4] + a.y * ctx[j * 4 + 1]
             + a.z * ctx[j * 4 + 2] + a.w * ctx[j * 4 + 3];
    }
#pragma unroll 8
    for (int j = 0; j < 64; j++) {
        float4 a = w2r[64 + j];
        acc += a.x * ht[j * 4] + a.y * ht[j * 4 + 1]
             + a.z * ht[j * 4 + 2] + a.w * ht[j * 4 + 3];
    }
    out[b * HH + tid] = tanhf(acc);
}

// ---------------------------------------------------------------------------
// Kernel 3: attention_weights.  grid=(TT/256, BB), block=256.  Fully parallel.
// ---------------------------------------------------------------------------
__global__ void __launch_bounds__(256) weights_kernel(float* __restrict__ out) {
    const int b = blockIdx.y;
    const int t = blockIdx.x * 256 + threadIdx.x;
    const float M = g_M[b];
    const float invL = g_invL[b];
    out[BB * HH + b * TT + t] = __expf(g_scores[b * TT + t] - M) * invL;
}

// ---------------------------------------------------------------------------
extern "C" void kernel_launch(void* const* d_in, const int* in_sizes, int n_in,
                              void* d_out, int out_size) {
    const float* hs = (const float*)d_in[0];   // (32, 8192, 256) f32
    const float* W1 = (const float*)d_in[1];   // (256, 256) f32
    const float* W2 = (const float*)d_in[2];   // (256, 512) f32
    float* out = (float*)d_out;

    vpart_kernel<<<dim3(BB, 8), 256>>>(hs, W1);
    vreduce_kernel<<<BB, 256>>>();
    pass1_kernel<<<dim3(NCH, BB), 256>>>(hs);
    merge_kernel<<<BB, 256>>>(hs, W2, out);
    weights_kernel<<<dim3(TT / 256, BB), 256>>>(out);
}

// round 4
// speedup vs baseline: 2.1111x; 1.2837x over previous
#include <cuda_runtime.h>
#include <cstdint>

#define BB 32
#define TT 8192
#define HH 256
#define CHUNK 128
#define NCH (TT / CHUNK)          // 64 chunks per batch
#define NSTAGE 2
#define SROWS 16
#define NSTG (CHUNK / SROWS)      // 8 stages per CTA
#define SBYTES (SROWS * HH * 4)   // 16 KB per stage

// Scratch (__device__ globals: allocation-free rule)
__device__ float g_vp[BB * 8 * HH];       // split-K partials of v
__device__ float g_v[BB * HH];            // v[b,h]
__device__ float g_scores[BB * TT];       // raw logits
__device__ float g_pm[BB * NCH];          // per-chunk max
__device__ float g_pl[BB * NCH];          // per-chunk sum-exp
__device__ float g_pc[BB * NCH * HH];     // per-chunk partial context
__device__ float g_ctx[BB * HH];          // normalized context
__device__ float g_M[BB];
__device__ float g_invL[BB];

// ---------------- mbarrier / bulk-async helpers ----------------
__device__ __forceinline__ uint32_t smem_u32(const void* p) {
    return (uint32_t)__cvta_generic_to_shared(p);
}
__device__ __forceinline__ void mbar_init(uint32_t a, uint32_t cnt) {
    asm volatile("mbarrier.init.shared.b64 [%0], %1;" :: "r"(a), "r"(cnt) : "memory");
}
__device__ __forceinline__ void mbar_expect_tx(uint32_t a, uint32_t bytes) {
    asm volatile("mbarrier.arrive.expect_tx.shared.b64 _, [%0], %1;"
                 :: "r"(a), "r"(bytes) : "memory");
}
__device__ __forceinline__ void mbar_arrive(uint32_t a) {
    asm volatile("mbarrier.arrive.shared.b64 _, [%0];" :: "r"(a) : "memory");
}
__device__ __forceinline__ void mbar_wait(uint32_t a, uint32_t parity) {
    asm volatile(
        "{\n\t.reg .pred P;\n\t"
        "LAB_%=:\n\t"
        "mbarrier.try_wait.parity.shared.b64 P, [%0], %1;\n\t"
        "@P bra.uni DONE_%=;\n\t"
        "bra.uni LAB_%=;\n\t"
        "DONE_%=:\n\t}"
        :: "r"(a), "r"(parity) : "memory");
}
__device__ __forceinline__ void bulk_g2s(uint32_t dst, const void* src,
                                         uint32_t bytes, uint32_t mbar) {
    asm volatile(
        "cp.async.bulk.shared::cluster.global.mbarrier::complete_tx::bytes "
        "[%0], [%1], %2, [%3];"
        :: "r"(dst), "l"(src), "r"(bytes), "r"(mbar) : "memory");
}

// ---------------------------------------------------------------------------
// Kernel 0a: split-K partial of v.  grid=(BB, 8), block=256.
// ---------------------------------------------------------------------------
__global__ void __launch_bounds__(256) vpart_kernel(const float* __restrict__ hs,
                                                    const float* __restrict__ W1) {
    const int b = blockIdx.x;
    const int s = blockIdx.y;
    const int h = threadIdx.x;
    __shared__ float ht[32];
    if (h < 32)
        ht[h] = hs[(size_t)b * TT * HH + (size_t)(TT - 1) * HH + s * 32 + h];
    __syncthreads();
    float acc = 0.f;
#pragma unroll
    for (int o = 0; o < 32; o++)
        acc += W1[(s * 32 + o) * HH + h] * ht[o];
    g_vp[(b * 8 + s) * HH + h] = acc;
}

// Kernel 0b: reduce partials.  grid=BB, block=256.
__global__ void __launch_bounds__(256) vreduce_kernel() {
    const int b = blockIdx.x;
    const int h = threadIdx.x;
    float a = 0.f;
#pragma unroll
    for (int s = 0; s < 8; s++) a += g_vp[(b * 8 + s) * HH + h];
    g_v[b * HH + h] = a;
}

// ---------------------------------------------------------------------------
// Kernel 1: bulk-async-staged fused score + online softmax + partial context.
// grid=(NCH, BB)=2048 CTAs, block=256 (8 warps).
// ---------------------------------------------------------------------------
__global__ void __launch_bounds__(256) pass1_kernel(const float* __restrict__ hs) {
    __shared__ __align__(16) float buf[NSTAGE][SROWS * HH];      // 32 KB
    __shared__ __align__(8) unsigned long long mb_full[NSTAGE];
    __shared__ __align__(8) unsigned long long mb_empty[NSTAGE];
    __shared__ float s_m[8], s_l[8];
    __shared__ float s_c[8][HH];                                  // 8 KB

    const int chunk = blockIdx.x;
    const int b = blockIdx.y;
    const int tid = threadIdx.x;
    const int w = tid >> 5;
    const int lane = tid & 31;

    uint32_t full_a[NSTAGE], empty_a[NSTAGE], buf_a[NSTAGE];
#pragma unroll
    for (int i = 0; i < NSTAGE; i++) {
        full_a[i] = smem_u32(&mb_full[i]);
        empty_a[i] = smem_u32(&mb_empty[i]);
        buf_a[i] = smem_u32(&buf[i][0]);
    }

    if (tid == 0) {
#pragma unroll
        for (int i = 0; i < NSTAGE; i++) {
            mbar_init(full_a[i], 1);
            mbar_init(empty_a[i], 8);
        }
    }
    __syncthreads();

    const float4* v4 = (const float4*)(g_v + b * HH);
    const float4 va = v4[lane];
    const float4 vb = v4[32 + lane];

    const char* src =
        (const char*)(hs + ((size_t)b * TT + (size_t)chunk * CHUNK) * HH);

    if (tid == 0) {
#pragma unroll
        for (int i = 0; i < NSTAGE; i++) {
            mbar_expect_tx(full_a[i], SBYTES);
            bulk_g2s(buf_a[i], src + (size_t)i * SBYTES, SBYTES, full_a[i]);
        }
    }

    float m = -1e30f, l = 0.f;
    float4 ca = make_float4(0.f, 0.f, 0.f, 0.f);
    float4 cb = make_float4(0.f, 0.f, 0.f, 0.f);
    float* scores = g_scores + b * TT + chunk * CHUNK;

    for (int s = 0; s < NSTG; s++) {
        const int slot = s & (NSTAGE - 1);
        mbar_wait(full_a[slot], (s / NSTAGE) & 1);

        const float4* bf = (const float4*)buf[slot];
#pragma unroll
        for (int rr = 0; rr < 2; rr++) {
            const int r = w * 2 + rr;
            float4 x1 = bf[r * 64 + lane];
            float4 x2 = bf[r * 64 + 32 + lane];
            float sc = x1.x * va.x + x1.y * va.y + x1.z * va.z + x1.w * va.w
                     + x2.x * vb.x + x2.y * vb.y + x2.z * vb.z + x2.w * vb.w;
#pragma unroll
            for (int off = 16; off; off >>= 1)
                sc += __shfl_xor_sync(0xffffffffu, sc, off);
            if (lane == 0) scores[s * SROWS + r] = sc;

            float mn = fmaxf(m, sc);
            float corr = __expf(m - mn);
            float p = __expf(sc - mn);
            l = l * corr + p;
            ca.x = ca.x * corr + p * x1.x;
            ca.y = ca.y * corr + p * x1.y;
            ca.z = ca.z * corr + p * x1.z;
            ca.w = ca.w * corr + p * x1.w;
            cb.x = cb.x * corr + p * x2.x;
            cb.y = cb.y * corr + p * x2.y;
            cb.z = cb.z * corr + p * x2.z;
            cb.w = cb.w * corr + p * x2.w;
            m = mn;
        }

        if (lane == 0) mbar_arrive(empty_a[slot]);

        if (tid == 0 && s + NSTAGE < NSTG) {
            const int ns = s + NSTAGE;
            mbar_wait(empty_a[slot], ((ns / NSTAGE) - 1) & 1);
            mbar_expect_tx(full_a[slot], SBYTES);
            bulk_g2s(buf_a[slot], src + (size_t)ns * SBYTES, SBYTES, full_a[slot]);
        }
    }

    if (lane == 0) { s_m[w] = m; s_l[w] = l; }
    s_c[w][lane * 4 + 0] = ca.x;
    s_c[w][lane * 4 + 1] = ca.y;
    s_c[w][lane * 4 + 2] = ca.z;
    s_c[w][lane * 4 + 3] = ca.w;
    s_c[w][128 + lane * 4 + 0] = cb.x;
    s_c[w][128 + lane * 4 + 1] = cb.y;
    s_c[w][128 + lane * 4 + 2] = cb.z;
    s_c[w][128 + lane * 4 + 3] = cb.w;
    __syncthreads();

    float M = -1e30f;
#pragma unroll
    for (int ww = 0; ww < 8; ww++) M = fmaxf(M, s_m[ww]);
    float L = 0.f, C = 0.f;
#pragma unroll
    for (int ww = 0; ww < 8; ww++) {
        float e = __expf(s_m[ww] - M);
        L += s_l[ww] * e;
        C += s_c[ww][tid] * e;
    }
    const int pidx = b * NCH + chunk;
    g_pc[pidx * HH + tid] = C;
    if (tid == 0) { g_pm[pidx] = M; g_pl[pidx] = L; }
}

// ---------------------------------------------------------------------------
// Kernel 2a: stats — merge 64 chunk partials per batch.  grid=BB, block=256.
// Writes g_ctx (normalized), g_M, g_invL.
// ---------------------------------------------------------------------------
__global__ void __launch_bounds__(256) stats_kernel() {
    const int b = blockIdx.x;
    const int tid = threadIdx.x;
    __shared__ float s_e[NCH];
    __shared__ float s_le[NCH];

    // per-thread redundant max over 64 values (L2-resident, coalesced-ish)
    float M = -1e30f;
#pragma unroll
    for (int i = 0; i < NCH; i++) M = fmaxf(M, g_pm[b * NCH + i]);

    if (tid < NCH) {
        float e = __expf(g_pm[b * NCH + tid] - M);
        s_e[tid] = e;
        s_le[tid] = g_pl[b * NCH + tid] * e;
    }
    __syncthreads();

    float L = 0.f;
#pragma unroll
    for (int i = 0; i < NCH; i++) L += s_le[i];
    const float invL = 1.f / L;

    // 4-way interleaved accumulators to expose MLP on the 64 coalesced loads
    const float* pc = g_pc + (size_t)b * NCH * HH + tid;
    float C0 = 0.f, C1 = 0.f, C2 = 0.f, C3 = 0.f;
#pragma unroll
    for (int i = 0; i < NCH; i += 4) {
        C0 += pc[(i + 0) * HH] * s_e[i + 0];
        C1 += pc[(i + 1) * HH] * s_e[i + 1];
        C2 += pc[(i + 2) * HH] * s_e[i + 2];
        C3 += pc[(i + 3) * HH] * s_e[i + 3];
    }
    g_ctx[b * HH + tid] = (C0 + C1 + C2 + C3) * invL;
    if (tid == 0) { g_M[b] = M; g_invL[b] = invL; }
}

// ---------------------------------------------------------------------------
// Kernel 2b: tanh head.  grid=(8, BB), block=256 (8 warps).
// Block computes 32 outputs; each warp 4 outputs with COALESCED W2 reads.
// ---------------------------------------------------------------------------
__global__ void __launch_bounds__(256) head_kernel(const float* __restrict__ hs,
                                                   const float* __restrict__ W2,
                                                   float* __restrict__ out) {
    const int b = blockIdx.y;
    const int tid = threadIdx.x;
    const int w = tid >> 5;
    const int lane = tid & 31;

    __shared__ __align__(16) float x[2 * HH];   // [ctx | ht]
    x[tid] = g_ctx[b * HH + tid];
    x[HH + tid] = hs[(size_t)b * TT * HH + (size_t)(TT - 1) * HH + tid];
    __syncthreads();

    const float4* x4 = (const float4*)x;        // 128 float4

    // 4 outputs per warp, interleaved for load MLP
    const int o0 = blockIdx.x * 32 + w * 4;
    float acc0 = 0.f, acc1 = 0.f, acc2 = 0.f, acc3 = 0.f;
    const float4* r0 = (const float4*)(W2 + (size_t)(o0 + 0) * 2 * HH);
    const float4* r1 = (const float4*)(W2 + (size_t)(o0 + 1) * 2 * HH);
    const float4* r2 = (const float4*)(W2 + (size_t)(o0 + 2) * 2 * HH);
    const float4* r3 = (const float4*)(W2 + (size_t)(o0 + 3) * 2 * HH);
#pragma unroll
    for (int k = 0; k < 4; k++) {
        const int j = lane + 32 * k;            // coalesced within warp
        float4 xv = x4[j];
        float4 a0 = r0[j], a1 = r1[j], a2 = r2[j], a3 = r3[j];
        acc0 += a0.x * xv.x + a0.y * xv.y + a0.z * xv.z + a0.w * xv.w;
        acc1 += a1.x * xv.x + a1.y * xv.y + a1.z * xv.z + a1.w * xv.w;
        acc2 += a2.x * xv.x + a2.y * xv.y + a2.z * xv.z + a2.w * xv.w;
        acc3 += a3.x * xv.x + a3.y * xv.y + a3.z * xv.z + a3.w * xv.w;
    }
#pragma unroll
    for (int off = 16; off; off >>= 1) {
        acc0 += __shfl_xor_sync(0xffffffffu, acc0, off);
        acc1 += __shfl_xor_sync(0xffffffffu, acc1, off);
        acc2 += __shfl_xor_sync(0xffffffffu, acc2, off);
        acc3 += __shfl_xor_sync(0xffffffffu, acc3, off);
    }
    if (lane == 0) {
        out[b * HH + o0 + 0] = tanhf(acc0);
        out[b * HH + o0 + 1] = tanhf(acc1);
        out[b * HH + o0 + 2] = tanhf(acc2);
        out[b * HH + o0 + 3] = tanhf(acc3);
    }
}

// ---------------------------------------------------------------------------
// Kernel 3: attention_weights.  grid=(TT/256, BB), block=256.
// ---------------------------------------------------------------------------
__global__ void __launch_bounds__(256) weights_kernel(float* __restrict__ out) {
    const int b = blockIdx.y;
    const int t = blockIdx.x * 256 + threadIdx.x;
    const float M = g_M[b];
    const float invL = g_invL[b];
    out[BB * HH + b * TT + t] = __expf(g_scores[b * TT + t] - M) * invL;
}

// ---------------------------------------------------------------------------
extern "C" void kernel_launch(void* const* d_in, const int* in_sizes, int n_in,
                              void* d_out, int out_size) {
    const float* hs = (const float*)d_in[0];   // (32, 8192, 256) f32
    const float* W1 = (const float*)d_in[1];   // (256, 256) f32
    const float* W2 = (const float*)d_in[2];   // (256, 512) f32
    float* out = (float*)d_out;

    vpart_kernel<<<dim3(BB, 8), 256>>>(hs, W1);
    vreduce_kernel<<<BB, 256>>>();
    pass1_kernel<<<dim3(NCH, BB), 256>>>(hs);
    stats_kernel<<<BB, 256>>>();
    weights_kernel<<<dim3(TT / 256, BB), 256>>>(out);
    head_kernel<<<dim3(8, BB), 256>>>(hs, W2, out);
}

// round 5
// speedup vs baseline: 2.1870x; 1.0360x over previous
#include <cuda_runtime.h>
#include <cstdint>

#define BB 32
#define TT 8192
#define HH 256
#define CHUNK 128
#define NCH (TT / CHUNK)          // 64 chunks per batch
#define NSTAGE 2
#define SROWS 16
#define NSTG (CHUNK / SROWS)      // 8 stages per CTA
#define SBYTES (SROWS * HH * 4)   // 16 KB per stage

// Scratch (__device__ globals: allocation-free rule)
__device__ float g_vp[BB * 8 * HH];       // split-K partials of v
__device__ float g_scores[BB * TT];       // raw logits
__device__ float g_pm[BB * NCH];          // per-chunk max
__device__ float g_pl[BB * NCH];          // per-chunk sum-exp
__device__ float g_pc[BB * NCH * HH];     // per-chunk partial context
__device__ float g_e[BB * NCH];           // exp(pm - M) per chunk
__device__ float g_M[BB];
__device__ float g_invL[BB];

// ---------------- mbarrier / bulk-async helpers ----------------
__device__ __forceinline__ uint32_t smem_u32(const void* p) {
    return (uint32_t)__cvta_generic_to_shared(p);
}
__device__ __forceinline__ void mbar_init(uint32_t a, uint32_t cnt) {
    asm volatile("mbarrier.init.shared.b64 [%0], %1;" :: "r"(a), "r"(cnt) : "memory");
}
__device__ __forceinline__ void mbar_expect_tx(uint32_t a, uint32_t bytes) {
    asm volatile("mbarrier.arrive.expect_tx.shared.b64 _, [%0], %1;"
                 :: "r"(a), "r"(bytes) : "memory");
}
__device__ __forceinline__ void mbar_arrive(uint32_t a) {
    asm volatile("mbarrier.arrive.shared.b64 _, [%0];" :: "r"(a) : "memory");
}
__device__ __forceinline__ void mbar_wait(uint32_t a, uint32_t parity) {
    asm volatile(
        "{\n\t.reg .pred P;\n\t"
        "LAB_%=:\n\t"
        "mbarrier.try_wait.parity.shared.b64 P, [%0], %1;\n\t"
        "@P bra.uni DONE_%=;\n\t"
        "bra.uni LAB_%=;\n\t"
        "DONE_%=:\n\t}"
        :: "r"(a), "r"(parity) : "memory");
}
__device__ __forceinline__ void bulk_g2s(uint32_t dst, const void* src,
                                         uint32_t bytes, uint32_t mbar) {
    asm volatile(
        "cp.async.bulk.shared::cluster.global.mbarrier::complete_tx::bytes "
        "[%0], [%1], %2, [%3];"
        :: "r"(dst), "l"(src), "r"(bytes), "r"(mbar) : "memory");
}

// ---------------------------------------------------------------------------
// Kernel 0: split-K partial of v.  grid=(BB, 8), block=256.
// vp[b,s,h] = sum_{o in [32s,32s+32)} W1[o,h] * h_t[b,o]
// (the final sum over s happens inside pass1's prologue)
// ---------------------------------------------------------------------------
__global__ void __launch_bounds__(256) vpart_kernel(const float* __restrict__ hs,
                                                    const float* __restrict__ W1) {
    const int b = blockIdx.x;
    const int s = blockIdx.y;
    const int h = threadIdx.x;
    __shared__ float ht[32];
    if (h < 32)
        ht[h] = hs[(size_t)b * TT * HH + (size_t)(TT - 1) * HH + s * 32 + h];
    __syncthreads();
    float acc = 0.f;
#pragma unroll
    for (int o = 0; o < 32; o++)
        acc += W1[(s * 32 + o) * HH + h] * ht[o];
    g_vp[(b * 8 + s) * HH + h] = acc;
}

// ---------------------------------------------------------------------------
// Kernel 1: bulk-async-staged fused score + online softmax + partial context.
// grid=(NCH, BB)=2048 CTAs, block=256 (8 warps).
// ---------------------------------------------------------------------------
__global__ void __launch_bounds__(256) pass1_kernel(const float* __restrict__ hs) {
    __shared__ __align__(16) float buf[NSTAGE][SROWS * HH];      // 32 KB
    __shared__ __align__(8) unsigned long long mb_full[NSTAGE];
    __shared__ __align__(8) unsigned long long mb_empty[NSTAGE];
    __shared__ float s_m[8], s_l[8];
    __shared__ float s_c[8][HH];                                  // 8 KB

    const int chunk = blockIdx.x;
    const int b = blockIdx.y;
    const int tid = threadIdx.x;
    const int w = tid >> 5;
    const int lane = tid & 31;

    uint32_t full_a[NSTAGE], empty_a[NSTAGE], buf_a[NSTAGE];
#pragma unroll
    for (int i = 0; i < NSTAGE; i++) {
        full_a[i] = smem_u32(&mb_full[i]);
        empty_a[i] = smem_u32(&mb_empty[i]);
        buf_a[i] = smem_u32(&buf[i][0]);
    }

    if (tid == 0) {
#pragma unroll
        for (int i = 0; i < NSTAGE; i++) {
            mbar_init(full_a[i], 1);
            mbar_init(empty_a[i], 8);
        }
    }
    __syncthreads();

    const char* src =
        (const char*)(hs + ((size_t)b * TT + (size_t)chunk * CHUNK) * HH);

    if (tid == 0) {
#pragma unroll
        for (int i = 0; i < NSTAGE; i++) {
            mbar_expect_tx(full_a[i], SBYTES);
            bulk_g2s(buf_a[i], src + (size_t)i * SBYTES, SBYTES, full_a[i]);
        }
    }

    // v slice for this lane = sum of the 8 split-K partials (L2-resident)
    const float4* vp4 = (const float4*)(g_vp) + (size_t)b * 8 * 64;
    float4 va = make_float4(0.f, 0.f, 0.f, 0.f);
    float4 vb = make_float4(0.f, 0.f, 0.f, 0.f);
#pragma unroll
    for (int s = 0; s < 8; s++) {
        float4 pa = vp4[s * 64 + lane];
        float4 pb = vp4[s * 64 + 32 + lane];
        va.x += pa.x; va.y += pa.y; va.z += pa.z; va.w += pa.w;
        vb.x += pb.x; vb.y += pb.y; vb.z += pb.z; vb.w += pb.w;
    }

    float m = -1e30f, l = 0.f;
    float4 ca = make_float4(0.f, 0.f, 0.f, 0.f);
    float4 cb = make_float4(0.f, 0.f, 0.f, 0.f);
    float* scores = g_scores + b * TT + chunk * CHUNK;

    for (int s = 0; s < NSTG; s++) {
        const int slot = s & (NSTAGE - 1);
        mbar_wait(full_a[slot], (s / NSTAGE) & 1);

        const float4* bf = (const float4*)buf[slot];
#pragma unroll
        for (int rr = 0; rr < 2; rr++) {
            const int r = w * 2 + rr;
            float4 x1 = bf[r * 64 + lane];
            float4 x2 = bf[r * 64 + 32 + lane];
            float sc = x1.x * va.x + x1.y * va.y + x1.z * va.z + x1.w * va.w
                     + x2.x * vb.x + x2.y * vb.y + x2.z * vb.z + x2.w * vb.w;
#pragma unroll
            for (int off = 16; off; off >>= 1)
                sc += __shfl_xor_sync(0xffffffffu, sc, off);
            if (lane == 0) scores[s * SROWS + r] = sc;

            float mn = fmaxf(m, sc);
            float corr = __expf(m - mn);
            float p = __expf(sc - mn);
            l = l * corr + p;
            ca.x = ca.x * corr + p * x1.x;
            ca.y = ca.y * corr + p * x1.y;
            ca.z = ca.z * corr + p * x1.z;
            ca.w = ca.w * corr + p * x1.w;
            cb.x = cb.x * corr + p * x2.x;
            cb.y = cb.y * corr + p * x2.y;
            cb.z = cb.z * corr + p * x2.z;
            cb.w = cb.w * corr + p * x2.w;
            m = mn;
        }

        if (lane == 0) mbar_arrive(empty_a[slot]);

        if (tid == 0 && s + NSTAGE < NSTG) {
            const int ns = s + NSTAGE;
            mbar_wait(empty_a[slot], ((ns / NSTAGE) - 1) & 1);
            mbar_expect_tx(full_a[slot], SBYTES);
            bulk_g2s(buf_a[slot], src + (size_t)ns * SBYTES, SBYTES, full_a[slot]);
        }
    }

    if (lane == 0) { s_m[w] = m; s_l[w] = l; }
    s_c[w][lane * 4 + 0] = ca.x;
    s_c[w][lane * 4 + 1] = ca.y;
    s_c[w][lane * 4 + 2] = ca.z;
    s_c[w][lane * 4 + 3] = ca.w;
    s_c[w][128 + lane * 4 + 0] = cb.x;
    s_c[w][128 + lane * 4 + 1] = cb.y;
    s_c[w][128 + lane * 4 + 2] = cb.z;
    s_c[w][128 + lane * 4 + 3] = cb.w;
    __syncthreads();

    float M = -1e30f;
#pragma unroll
    for (int ww = 0; ww < 8; ww++) M = fmaxf(M, s_m[ww]);
    float L = 0.f, C = 0.f;
#pragma unroll
    for (int ww = 0; ww < 8; ww++) {
        float e = __expf(s_m[ww] - M);
        L += s_l[ww] * e;
        C += s_c[ww][tid] * e;
    }
    const int pidx = b * NCH + chunk;
    g_pc[pidx * HH + tid] = C;
    if (tid == 0) { g_pm[pidx] = M; g_pl[pidx] = L; }
}

// ---------------------------------------------------------------------------
// Kernel 2: scalar stats only.  grid=BB, block=NCH(=64).
// Computes M[b], invL[b] and per-chunk e-factors g_e (all L2-hot, tiny).
// ---------------------------------------------------------------------------
__global__ void __launch_bounds__(64) stats_kernel() {
    const int b = blockIdx.x;
    const int tid = threadIdx.x;
    __shared__ float sm[NCH];
    __shared__ float sl[NCH];

    const float pm = g_pm[b * NCH + tid];
    sm[tid] = pm;
    __syncthreads();
    float M = -1e30f;
#pragma unroll
    for (int i = 0; i < NCH; i++) M = fmaxf(M, sm[i]);

    const float e = __expf(pm - M);
    sl[tid] = g_pl[b * NCH + tid] * e;
    g_e[b * NCH + tid] = e;
    __syncthreads();
    if (tid == 0) {
        float L = 0.f;
#pragma unroll
        for (int i = 0; i < NCH; i++) L += sl[i];
        g_M[b] = M;
        g_invL[b] = 1.f / L;
    }
}

// ---------------------------------------------------------------------------
// Kernel 3: attention_weights.  grid=(TT/256, BB), block=256.
// ---------------------------------------------------------------------------
__global__ void __launch_bounds__(256) weights_kernel(float* __restrict__ out) {
    const int b = blockIdx.y;
    const int t = blockIdx.x * 256 + threadIdx.x;
    const float M = g_M[b];
    const float invL = g_invL[b];
    out[BB * HH + b * TT + t] = __expf(g_scores[b * TT + t] - M) * invL;
}

// ---------------------------------------------------------------------------
// Kernel 4: tanh head.  grid=(8, BB), block=256 (8 warps).
// Each block recomputes ctx from L2-resident g_pc (parallel redundancy),
// then each warp produces 4 outputs with coalesced W2 reads.
// ---------------------------------------------------------------------------
__global__ void __launch_bounds__(256) head_kernel(const float* __restrict__ hs,
                                                   const float* __restrict__ W2,
                                                   float* __restrict__ out) {
    const int b = blockIdx.y;
    const int tid = threadIdx.x;
    const int w = tid >> 5;
    const int lane = tid & 31;

    __shared__ float s_e[NCH];
    __shared__ __align__(16) float x[2 * HH];   // [ctx | ht]

    if (tid < NCH) s_e[tid] = g_e[b * NCH + tid];
    x[HH + tid] = hs[(size_t)b * TT * HH + (size_t)(TT - 1) * HH + tid];
    __syncthreads();

    // ctx[tid] = invL * sum_i pc[i][tid] * e[i]  (64 coalesced L2 loads)
    const float* pc = g_pc + (size_t)b * NCH * HH + tid;
    float C0 = 0.f, C1 = 0.f, C2 = 0.f, C3 = 0.f;
#pragma unroll
    for (int i = 0; i < NCH; i += 4) {
        C0 += pc[(i + 0) * HH] * s_e[i + 0];
        C1 += pc[(i + 1) * HH] * s_e[i + 1];
        C2 += pc[(i + 2) * HH] * s_e[i + 2];
        C3 += pc[(i + 3) * HH] * s_e[i + 3];
    }
    x[tid] = (C0 + C1 + C2 + C3) * g_invL[b];
    __syncthreads();

    const float4* x4 = (const float4*)x;        // 128 float4

    const int o0 = blockIdx.x * 32 + w * 4;
    float acc0 = 0.f, acc1 = 0.f, acc2 = 0.f, acc3 = 0.f;
    const float4* r0 = (const float4*)(W2 + (size_t)(o0 + 0) * 2 * HH);
    const float4* r1 = (const float4*)(W2 + (size_t)(o0 + 1) * 2 * HH);
    const float4* r2 = (const float4*)(W2 + (size_t)(o0 + 2) * 2 * HH);
    const float4* r3 = (const float4*)(W2 + (size_t)(o0 + 3) * 2 * HH);
#pragma unroll
    for (int k = 0; k < 4; k++) {
        const int j = lane + 32 * k;            // coalesced within warp
        float4 xv = x4[j];
        float4 a0 = r0[j], a1 = r1[j], a2 = r2[j], a3 = r3[j];
        acc0 += a0.x * xv.x + a0.y * xv.y + a0.z * xv.z + a0.w * xv.w;
        acc1 += a1.x * xv.x + a1.y * xv.y + a1.z * xv.z + a1.w * xv.w;
        acc2 += a2.x * xv.x + a2.y * xv.y + a2.z * xv.z + a2.w * xv.w;
        acc3 += a3.x * xv.x + a3.y * xv.y + a3.z * xv.z + a3.w * xv.w;
    }
#pragma unroll
    for (int off = 16; off; off >>= 1) {
        acc0 += __shfl_xor_sync(0xffffffffu, acc0, off);
        acc1 += __shfl_xor_sync(0xffffffffu, acc1, off);
        acc2 += __shfl_xor_sync(0xffffffffu, acc2, off);
        acc3 += __shfl_xor_sync(0xffffffffu, acc3, off);
    }
    if (lane == 0) {
        out[b * HH + o0 + 0] = tanhf(acc0);
        out[b * HH + o0 + 1] = tanhf(acc1);
        out[b * HH + o0 + 2] = tanhf(acc2);
        out[b * HH + o0 + 3] = tanhf(acc3);
    }
}

// ---------------------------------------------------------------------------
extern "C" void kernel_launch(void* const* d_in, const int* in_sizes, int n_in,
                              void* d_out, int out_size) {
    const float* hs = (const float*)d_in[0];   // (32, 8192, 256) f32
    const float* W1 = (const float*)d_in[1];   // (256, 256) f32
    const float* W2 = (const float*)d_in[2];   // (256, 512) f32
    float* out = (float*)d_out;

    vpart_kernel<<<dim3(BB, 8), 256>>>(hs, W1);
    pass1_kernel<<<dim3(NCH, BB), 256>>>(hs);
    stats_kernel<<<BB, 64>>>();
    weights_kernel<<<dim3(TT / 256, BB), 256>>>(out);
    head_kernel<<<dim3(8, BB), 256>>>(hs, W2, out);
}

// round 6
// speedup vs baseline: 2.6007x; 1.1892x over previous
#include <cuda_runtime.h>
#include <cstdint>

#define BB 32
#define TT 8192
#define HH 256
#define CHUNK 128
#define NCH (TT / CHUNK)          // 64 chunks per batch
#define NSTAGE 3
#define SROWS 16
#define NSTG (CHUNK / SROWS)      // 8 stages per CTA
#define SBYTES (SROWS * HH * 4)   // 16 KB per stage

// Scratch (__device__ globals: allocation-free rule)
__device__ float g_vp[BB * 8 * HH];       // split-K partials of v
__device__ float g_scores[BB * TT];       // raw logits
__device__ float g_pm[BB * NCH];          // per-chunk max
__device__ float g_pl[BB * NCH];          // per-chunk sum-exp
__device__ float g_pc[BB * NCH * HH];     // per-chunk partial context
__device__ float g_e[BB * NCH];           // exp(pm - M) per chunk
__device__ float g_M[BB];
__device__ float g_invL[BB];

// ---------------- mbarrier / bulk-async helpers ----------------
__device__ __forceinline__ uint32_t smem_u32(const void* p) {
    return (uint32_t)__cvta_generic_to_shared(p);
}
__device__ __forceinline__ void mbar_init(uint32_t a, uint32_t cnt) {
    asm volatile("mbarrier.init.shared.b64 [%0], %1;" :: "r"(a), "r"(cnt) : "memory");
}
__device__ __forceinline__ void mbar_expect_tx(uint32_t a, uint32_t bytes) {
    asm volatile("mbarrier.arrive.expect_tx.shared.b64 _, [%0], %1;"
                 :: "r"(a), "r"(bytes) : "memory");
}
__device__ __forceinline__ void mbar_arrive(uint32_t a) {
    asm volatile("mbarrier.arrive.shared.b64 _, [%0];" :: "r"(a) : "memory");
}
__device__ __forceinline__ void mbar_wait(uint32_t a, uint32_t parity) {
    asm volatile(
        "{\n\t.reg .pred P;\n\t"
        "LAB_%=:\n\t"
        "mbarrier.try_wait.parity.shared.b64 P, [%0], %1;\n\t"
        "@P bra.uni DONE_%=;\n\t"
        "bra.uni LAB_%=;\n\t"
        "DONE_%=:\n\t}"
        :: "r"(a), "r"(parity) : "memory");
}
__device__ __forceinline__ void bulk_g2s(uint32_t dst, const void* src,
                                         uint32_t bytes, uint32_t mbar) {
    asm volatile(
        "cp.async.bulk.shared::cluster.global.mbarrier::complete_tx::bytes "
        "[%0], [%1], %2, [%3];"
        :: "r"(dst), "l"(src), "r"(bytes), "r"(mbar) : "memory");
}

// ---------------------------------------------------------------------------
// Kernel 0: split-K partial of v.  grid=(BB, 8), block=256.
// ---------------------------------------------------------------------------
__global__ void __launch_bounds__(256) vpart_kernel(const float* __restrict__ hs,
                                                    const float* __restrict__ W1) {
    const int b = blockIdx.x;
    const int s = blockIdx.y;
    const int h = threadIdx.x;
    __shared__ float ht[32];
    if (h < 32)
        ht[h] = hs[(size_t)b * TT * HH + (size_t)(TT - 1) * HH + s * 32 + h];
    __syncthreads();
    float acc = 0.f;
#pragma unroll
    for (int o = 0; o < 32; o++)
        acc += W1[(s * 32 + o) * HH + h] * ht[o];
    g_vp[(b * 8 + s) * HH + h] = acc;
}

// ---------------------------------------------------------------------------
// Kernel 1: bulk-async-staged fused score + online softmax + partial context.
// grid=(NCH, BB)=2048 CTAs, block=256 (8 warps), 3-stage 16 KB ring.
// Per stage each warp processes 2 INDEPENDENT rows with a single fused
// rescale (one max, one corr, two exps).
// ---------------------------------------------------------------------------
__global__ void __launch_bounds__(256) pass1_kernel(const float* __restrict__ hs) {
    __shared__ __align__(16) float buf[NSTAGE][SROWS * HH];      // 48 KB
    __shared__ __align__(8) unsigned long long mb_full[NSTAGE];
    __shared__ __align__(8) unsigned long long mb_empty[NSTAGE];
    __shared__ float s_m[8], s_l[8];
    __shared__ float s_c[8][HH];                                  // 8 KB

    const int chunk = blockIdx.x;
    const int b = blockIdx.y;
    const int tid = threadIdx.x;
    const int w = tid >> 5;
    const int lane = tid & 31;

    uint32_t full_a[NSTAGE], empty_a[NSTAGE], buf_a[NSTAGE];
#pragma unroll
    for (int i = 0; i < NSTAGE; i++) {
        full_a[i] = smem_u32(&mb_full[i]);
        empty_a[i] = smem_u32(&mb_empty[i]);
        buf_a[i] = smem_u32(&buf[i][0]);
    }

    if (tid == 0) {
#pragma unroll
        for (int i = 0; i < NSTAGE; i++) {
            mbar_init(full_a[i], 1);
            mbar_init(empty_a[i], 8);
        }
    }
    __syncthreads();

    const char* src =
        (const char*)(hs + ((size_t)b * TT + (size_t)chunk * CHUNK) * HH);

    if (tid == 0) {
#pragma unroll
        for (int i = 0; i < NSTAGE; i++) {
            mbar_expect_tx(full_a[i], SBYTES);
            bulk_g2s(buf_a[i], src + (size_t)i * SBYTES, SBYTES, full_a[i]);
        }
    }

    // v slice for this lane = sum of the 8 split-K partials (L2-resident)
    const float4* vp4 = (const float4*)(g_vp) + (size_t)b * 8 * 64;
    float4 va = make_float4(0.f, 0.f, 0.f, 0.f);
    float4 vb = make_float4(0.f, 0.f, 0.f, 0.f);
#pragma unroll
    for (int s = 0; s < 8; s++) {
        float4 pa = vp4[s * 64 + lane];
        float4 pb = vp4[s * 64 + 32 + lane];
        va.x += pa.x; va.y += pa.y; va.z += pa.z; va.w += pa.w;
        vb.x += pb.x; vb.y += pb.y; vb.z += pb.z; vb.w += pb.w;
    }

    float m = -1e30f, l = 0.f;
    float4 ca = make_float4(0.f, 0.f, 0.f, 0.f);
    float4 cb = make_float4(0.f, 0.f, 0.f, 0.f);
    float* scores = g_scores + b * TT + chunk * CHUNK;

    for (int s = 0; s < NSTG; s++) {
        const int slot = s % NSTAGE;
        mbar_wait(full_a[slot], (s / NSTAGE) & 1);

        const float4* bf = (const float4*)buf[slot];
        const int r0 = w * 2;
        // row 0 vectors
        float4 a0 = bf[r0 * 64 + lane];
        float4 a1 = bf[r0 * 64 + 32 + lane];
        // row 1 vectors
        float4 b0 = bf[(r0 + 1) * 64 + lane];
        float4 b1 = bf[(r0 + 1) * 64 + 32 + lane];

        float s0 = a0.x * va.x + a0.y * va.y + a0.z * va.z + a0.w * va.w
                 + a1.x * vb.x + a1.y * vb.y + a1.z * vb.z + a1.w * vb.w;
        float s1 = b0.x * va.x + b0.y * va.y + b0.z * va.z + b0.w * va.w
                 + b1.x * vb.x + b1.y * vb.y + b1.z * vb.z + b1.w * vb.w;
#pragma unroll
        for (int off = 16; off; off >>= 1) {
            s0 += __shfl_xor_sync(0xffffffffu, s0, off);
            s1 += __shfl_xor_sync(0xffffffffu, s1, off);
        }
        if (lane == 0)
            *(float2*)(scores + s * SROWS + r0) = make_float2(s0, s1);

        // single fused rescale for both rows
        float mn = fmaxf(m, fmaxf(s0, s1));
        float corr = __expf(m - mn);
        float p0 = __expf(s0 - mn);
        float p1 = __expf(s1 - mn);
        l = l * corr + p0 + p1;
        ca.x = ca.x * corr + p0 * a0.x + p1 * b0.x;
        ca.y = ca.y * corr + p0 * a0.y + p1 * b0.y;
        ca.z = ca.z * corr + p0 * a0.z + p1 * b0.z;
        ca.w = ca.w * corr + p0 * a0.w + p1 * b0.w;
        cb.x = cb.x * corr + p0 * a1.x + p1 * b1.x;
        cb.y = cb.y * corr + p0 * a1.y + p1 * b1.y;
        cb.z = cb.z * corr + p0 * a1.z + p1 * b1.z;
        cb.w = cb.w * corr + p0 * a1.w + p1 * b1.w;
        m = mn;

        if (lane == 0) mbar_arrive(empty_a[slot]);

        if (tid == 0 && s + NSTAGE < NSTG) {
            const int ns = s + NSTAGE;
            mbar_wait(empty_a[slot], ((ns / NSTAGE) - 1) & 1);
            mbar_expect_tx(full_a[slot], SBYTES);
            bulk_g2s(buf_a[slot], src + (size_t)ns * SBYTES, SBYTES, full_a[slot]);
        }
    }

    if (lane == 0) { s_m[w] = m; s_l[w] = l; }
    s_c[w][lane * 4 + 0] = ca.x;
    s_c[w][lane * 4 + 1] = ca.y;
    s_c[w][lane * 4 + 2] = ca.z;
    s_c[w][lane * 4 + 3] = ca.w;
    s_c[w][128 + lane * 4 + 0] = cb.x;
    s_c[w][128 + lane * 4 + 1] = cb.y;
    s_c[w][128 + lane * 4 + 2] = cb.z;
    s_c[w][128 + lane * 4 + 3] = cb.w;
    __syncthreads();

    float M = -1e30f;
#pragma unroll
    for (int ww = 0; ww < 8; ww++) M = fmaxf(M, s_m[ww]);
    float L = 0.f, C = 0.f;
#pragma unroll
    for (int ww = 0; ww < 8; ww++) {
        float e = __expf(s_m[ww] - M);
        L += s_l[ww] * e;
        C += s_c[ww][tid] * e;
    }
    const int pidx = b * NCH + chunk;
    g_pc[pidx * HH + tid] = C;
    if (tid == 0) { g_pm[pidx] = M; g_pl[pidx] = L; }
}

// ---------------------------------------------------------------------------
// Kernel 2: scalar stats.  grid=BB, block=NCH(=64).
// ---------------------------------------------------------------------------
__global__ void __launch_bounds__(64) stats_kernel() {
    const int b = blockIdx.x;
    const int tid = threadIdx.x;
    __shared__ float sm[NCH];
    __shared__ float sl[NCH];

    const float pm = g_pm[b * NCH + tid];
    sm[tid] = pm;
    __syncthreads();
    float M = -1e30f;
#pragma unroll
    for (int i = 0; i < NCH; i++) M = fmaxf(M, sm[i]);

    const float e = __expf(pm - M);
    sl[tid] = g_pl[b * NCH + tid] * e;
    g_e[b * NCH + tid] = e;
    __syncthreads();
    if (tid == 0) {
        float L = 0.f;
#pragma unroll
        for (int i = 0; i < NCH; i++) L += sl[i];
        g_M[b] = M;
        g_invL[b] = 1.f / L;
    }
}

// ---------------------------------------------------------------------------
// Kernel 3: attention_weights, vectorized.  grid=(TT/1024, BB), block=256.
// Each thread handles 4 consecutive t.
// ---------------------------------------------------------------------------
__global__ void __launch_bounds__(256) weights_kernel(float* __restrict__ out) {
    const int b = blockIdx.y;
    const int t4 = blockIdx.x * 256 + threadIdx.x;   // float4 index
    const float M = g_M[b];
    const float invL = g_invL[b];
    float4 sc = ((const float4*)(g_scores + b * TT))[t4];
    float4 r;
    r.x = __expf(sc.x - M) * invL;
    r.y = __expf(sc.y - M) * invL;
    r.z = __expf(sc.z - M) * invL;
    r.w = __expf(sc.w - M) * invL;
    ((float4*)(out + BB * HH + b * TT))[t4] = r;
}

// ---------------------------------------------------------------------------
// Kernel 4: tanh head.  grid=(8, BB), block=256 (8 warps).
// ---------------------------------------------------------------------------
__global__ void __launch_bounds__(256) head_kernel(const float* __restrict__ hs,
                                                   const float* __restrict__ W2,
                                                   float* __restrict__ out) {
    const int b = blockIdx.y;
    const int tid = threadIdx.x;
    const int w = tid >> 5;
    const int lane = tid & 31;

    __shared__ float s_e[NCH];
    __shared__ __align__(16) float x[2 * HH];   // [ctx | ht]

    if (tid < NCH) s_e[tid] = g_e[b * NCH + tid];
    x[HH + tid] = hs[(size_t)b * TT * HH + (size_t)(TT - 1) * HH + tid];
    __syncthreads();

    const float* pc = g_pc + (size_t)b * NCH * HH + tid;
    float C0 = 0.f, C1 = 0.f, C2 = 0.f, C3 = 0.f;
#pragma unroll
    for (int i = 0; i < NCH; i += 4) {
        C0 += pc[(i + 0) * HH] * s_e[i + 0];
        C1 += pc[(i + 1) * HH] * s_e[i + 1];
        C2 += pc[(i + 2) * HH] * s_e[i + 2];
        C3 += pc[(i + 3) * HH] * s_e[i + 3];
    }
    x[tid] = (C0 + C1 + C2 + C3) * g_invL[b];
    __syncthreads();

    const float4* x4 = (const float4*)x;        // 128 float4

    const int o0 = blockIdx.x * 32 + w * 4;
    float acc0 = 0.f, acc1 = 0.f, acc2 = 0.f, acc3 = 0.f;
    const float4* r0 = (const float4*)(W2 + (size_t)(o0 + 0) * 2 * HH);
    const float4* r1 = (const float4*)(W2 + (size_t)(o0 + 1) * 2 * HH);
    const float4* r2 = (const float4*)(W2 + (size_t)(o0 + 2) * 2 * HH);
    const float4* r3 = (const float4*)(W2 + (size_t)(o0 + 3) * 2 * HH);
#pragma unroll
    for (int k = 0; k < 4; k++) {
        const int j = lane + 32 * k;            // coalesced within warp
        float4 xv = x4[j];
        float4 a0 = r0[j], a1 = r1[j], a2 = r2[j], a3 = r3[j];
        acc0 += a0.x * xv.x + a0.y * xv.y + a0.z * xv.z + a0.w * xv.w;
        acc1 += a1.x * xv.x + a1.y * xv.y + a1.z * xv.z + a1.w * xv.w;
        acc2 += a2.x * xv.x + a2.y * xv.y + a2.z * xv.z + a2.w * xv.w;
        acc3 += a3.x * xv.x + a3.y * xv.y + a3.z * xv.z + a3.w * xv.w;
    }
#pragma unroll
    for (int off = 16; off; off >>= 1) {
        acc0 += __shfl_xor_sync(0xffffffffu, acc0, off);
        acc1 += __shfl_xor_sync(0xffffffffu, acc1, off);
        acc2 += __shfl_xor_sync(0xffffffffu, acc2, off);
        acc3 += __shfl_xor_sync(0xffffffffu, acc3, off);
    }
    if (lane == 0) {
        out[b * HH + o0 + 0] = tanhf(acc0);
        out[b * HH + o0 + 1] = tanhf(acc1);
        out[b * HH + o0 + 2] = tanhf(acc2);
        out[b * HH + o0 + 3] = tanhf(acc3);
    }
}

// ---------------------------------------------------------------------------
extern "C" void kernel_launch(void* const* d_in, const int* in_sizes, int n_in,
                              void* d_out, int out_size) {
    const float* hs = (const float*)d_in[0];   // (32, 8192, 256) f32
    const float* W1 = (const float*)d_in[1];   // (256, 256) f32
    const float* W2 = (const float*)d_in[2];   // (256, 512) f32
    float* out = (float*)d_out;

    vpart_kernel<<<dim3(BB, 8), 256>>>(hs, W1);
    pass1_kernel<<<dim3(NCH, BB), 256>>>(hs);
    stats_kernel<<<BB, 64>>>();
    weights_kernel<<<dim3(TT / 1024, BB), 256>>>(out);
    head_kernel<<<dim3(8, BB), 256>>>(hs, W2, out);
}

// round 7
// speedup vs baseline: 2.6331x; 1.0124x over previous
#include <cuda_runtime.h>
#include <cstdint>

#define BB 32
#define TT 8192
#define HH 256
#define CHUNK 128
#define NCH (TT / CHUNK)          // 64 chunks per batch
#define NSTAGE 2
#define SROWS 32
#define NSTG (CHUNK / SROWS)      // 4 stages per CTA
#define SBYTES (SROWS * HH * 4)   // 32 KB per stage

// Scratch (__device__ globals: allocation-free rule)
__device__ float g_vp[BB * 8 * HH];       // split-K partials of v
__device__ float g_scores[BB * TT];       // raw logits
__device__ float g_pm[BB * NCH];          // per-chunk max
__device__ float g_pl[BB * NCH];          // per-chunk sum-exp
__device__ float g_pc[BB * NCH * HH];     // per-chunk partial context

// ---------------- mbarrier / bulk-async helpers ----------------
__device__ __forceinline__ uint32_t smem_u32(const void* p) {
    return (uint32_t)__cvta_generic_to_shared(p);
}
__device__ __forceinline__ void mbar_init(uint32_t a, uint32_t cnt) {
    asm volatile("mbarrier.init.shared.b64 [%0], %1;" :: "r"(a), "r"(cnt) : "memory");
}
__device__ __forceinline__ void mbar_expect_tx(uint32_t a, uint32_t bytes) {
    asm volatile("mbarrier.arrive.expect_tx.shared.b64 _, [%0], %1;"
                 :: "r"(a), "r"(bytes) : "memory");
}
__device__ __forceinline__ void mbar_arrive(uint32_t a) {
    asm volatile("mbarrier.arrive.shared.b64 _, [%0];" :: "r"(a) : "memory");
}
__device__ __forceinline__ void mbar_wait(uint32_t a, uint32_t parity) {
    asm volatile(
        "{\n\t.reg .pred P;\n\t"
        "LAB_%=:\n\t"
        "mbarrier.try_wait.parity.shared.b64 P, [%0], %1;\n\t"
        "@P bra.uni DONE_%=;\n\t"
        "bra.uni LAB_%=;\n\t"
        "DONE_%=:\n\t}"
        :: "r"(a), "r"(parity) : "memory");
}
__device__ __forceinline__ void bulk_g2s(uint32_t dst, const void* src,
                                         uint32_t bytes, uint32_t mbar) {
    asm volatile(
        "cp.async.bulk.shared::cluster.global.mbarrier::complete_tx::bytes "
        "[%0], [%1], %2, [%3];"
        :: "r"(dst), "l"(src), "r"(bytes), "r"(mbar) : "memory");
}

// ---------------------------------------------------------------------------
// Kernel 0: split-K partial of v.  grid=(BB, 8), block=256.
// ---------------------------------------------------------------------------
__global__ void __launch_bounds__(256) vpart_kernel(const float* __restrict__ hs,
                                                    const float* __restrict__ W1) {
    const int b = blockIdx.x;
    const int s = blockIdx.y;
    const int h = threadIdx.x;
    __shared__ float ht[32];
    if (h < 32)
        ht[h] = hs[(size_t)b * TT * HH + (size_t)(TT - 1) * HH + s * 32 + h];
    __syncthreads();
    float acc = 0.f;
#pragma unroll
    for (int o = 0; o < 32; o++)
        acc += W1[(s * 32 + o) * HH + h] * ht[o];
    g_vp[(b * 8 + s) * HH + h] = acc;
}

// ---------------------------------------------------------------------------
// Kernel 1: bulk-async-staged fused score + online softmax + partial context.
// grid=(NCH, BB)=2048 CTAs, block=256 (8 warps), 2-stage 32 KB dynamic-smem
// ring.  Per stage each warp processes 4 rows with ONE fused rescale.
// ---------------------------------------------------------------------------
extern __shared__ __align__(16) float dynbuf[];   // NSTAGE * SROWS * HH floats

__global__ void __launch_bounds__(256) pass1_kernel(const float* __restrict__ hs) {
    __shared__ __align__(8) unsigned long long mb_full[NSTAGE];
    __shared__ __align__(8) unsigned long long mb_empty[NSTAGE];
    __shared__ float s_m[8], s_l[8];
    __shared__ float s_c[8][HH];                                  // 8 KB

    const int chunk = blockIdx.x;
    const int b = blockIdx.y;
    const int tid = threadIdx.x;
    const int w = tid >> 5;
    const int lane = tid & 31;

    uint32_t full_a[NSTAGE], empty_a[NSTAGE], buf_a[NSTAGE];
#pragma unroll
    for (int i = 0; i < NSTAGE; i++) {
        full_a[i] = smem_u32(&mb_full[i]);
        empty_a[i] = smem_u32(&mb_empty[i]);
        buf_a[i] = smem_u32(&dynbuf[i * SROWS * HH]);
    }

    if (tid == 0) {
#pragma unroll
        for (int i = 0; i < NSTAGE; i++) {
            mbar_init(full_a[i], 1);
            mbar_init(empty_a[i], 8);
        }
    }
    __syncthreads();

    const char* src =
        (const char*)(hs + ((size_t)b * TT + (size_t)chunk * CHUNK) * HH);

    if (tid == 0) {
#pragma unroll
        for (int i = 0; i < NSTAGE; i++) {
            mbar_expect_tx(full_a[i], SBYTES);
            bulk_g2s(buf_a[i], src + (size_t)i * SBYTES, SBYTES, full_a[i]);
        }
    }

    // v slice for this lane = sum of the 8 split-K partials (L2-resident)
    const float4* vp4 = (const float4*)(g_vp) + (size_t)b * 8 * 64;
    float4 va = make_float4(0.f, 0.f, 0.f, 0.f);
    float4 vb = make_float4(0.f, 0.f, 0.f, 0.f);
#pragma unroll
    for (int s = 0; s < 8; s++) {
        float4 pa = vp4[s * 64 + lane];
        float4 pb = vp4[s * 64 + 32 + lane];
        va.x += pa.x; va.y += pa.y; va.z += pa.z; va.w += pa.w;
        vb.x += pb.x; vb.y += pb.y; vb.z += pb.z; vb.w += pb.w;
    }

    float m = -1e30f, l = 0.f;
    float4 ca = make_float4(0.f, 0.f, 0.f, 0.f);
    float4 cb = make_float4(0.f, 0.f, 0.f, 0.f);
    float* scores = g_scores + b * TT + chunk * CHUNK;

    for (int s = 0; s < NSTG; s++) {
        const int slot = s & (NSTAGE - 1);
        mbar_wait(full_a[slot], (s / NSTAGE) & 1);

        const float4* bf = (const float4*)(dynbuf + slot * SROWS * HH);
        const int r0 = w * 4;
        // 4 rows, two float4 halves each
        float4 x0a = bf[(r0 + 0) * 64 + lane], x0b = bf[(r0 + 0) * 64 + 32 + lane];
        float4 x1a = bf[(r0 + 1) * 64 + lane], x1b = bf[(r0 + 1) * 64 + 32 + lane];
        float4 x2a = bf[(r0 + 2) * 64 + lane], x2b = bf[(r0 + 2) * 64 + 32 + lane];
        float4 x3a = bf[(r0 + 3) * 64 + lane], x3b = bf[(r0 + 3) * 64 + 32 + lane];

        float s0 = x0a.x * va.x + x0a.y * va.y + x0a.z * va.z + x0a.w * va.w
                 + x0b.x * vb.x + x0b.y * vb.y + x0b.z * vb.z + x0b.w * vb.w;
        float s1 = x1a.x * va.x + x1a.y * va.y + x1a.z * va.z + x1a.w * va.w
                 + x1b.x * vb.x + x1b.y * vb.y + x1b.z * vb.z + x1b.w * vb.w;
        float s2 = x2a.x * va.x + x2a.y * va.y + x2a.z * va.z + x2a.w * va.w
                 + x2b.x * vb.x + x2b.y * vb.y + x2b.z * vb.z + x2b.w * vb.w;
        float s3 = x3a.x * va.x + x3a.y * va.y + x3a.z * va.z + x3a.w * va.w
                 + x3b.x * vb.x + x3b.y * vb.y + x3b.z * vb.z + x3b.w * vb.w;
#pragma unroll
        for (int off = 16; off; off >>= 1) {
            s0 += __shfl_xor_sync(0xffffffffu, s0, off);
            s1 += __shfl_xor_sync(0xffffffffu, s1, off);
            s2 += __shfl_xor_sync(0xffffffffu, s2, off);
            s3 += __shfl_xor_sync(0xffffffffu, s3, off);
        }
        if (lane == 0)
            *(float4*)(scores + s * SROWS + r0) = make_float4(s0, s1, s2, s3);

        // single fused rescale for 4 rows
        float mn = fmaxf(fmaxf(m, fmaxf(s0, s1)), fmaxf(s2, s3));
        float corr = __expf(m - mn);
        float p0 = __expf(s0 - mn);
        float p1 = __expf(s1 - mn);
        float p2 = __expf(s2 - mn);
        float p3 = __expf(s3 - mn);
        l = l * corr + p0 + p1 + p2 + p3;
        ca.x = ca.x * corr + p0 * x0a.x + p1 * x1a.x + p2 * x2a.x + p3 * x3a.x;
        ca.y = ca.y * corr + p0 * x0a.y + p1 * x1a.y + p2 * x2a.y + p3 * x3a.y;
        ca.z = ca.z * corr + p0 * x0a.z + p1 * x1a.z + p2 * x2a.z + p3 * x3a.z;
        ca.w = ca.w * corr + p0 * x0a.w + p1 * x1a.w + p2 * x2a.w + p3 * x3a.w;
        cb.x = cb.x * corr + p0 * x0b.x + p1 * x1b.x + p2 * x2b.x + p3 * x3b.x;
        cb.y = cb.y * corr + p0 * x0b.y + p1 * x1b.y + p2 * x2b.y + p3 * x3b.y;
        cb.z = cb.z * corr + p0 * x0b.z + p1 * x1b.z + p2 * x2b.z + p3 * x3b.z;
        cb.w = cb.w * corr + p0 * x0b.w + p1 * x1b.w + p2 * x2b.w + p3 * x3b.w;
        m = mn;

        if (lane == 0) mbar_arrive(empty_a[slot]);

        if (tid == 0 && s + NSTAGE < NSTG) {
            const int ns = s + NSTAGE;
            mbar_wait(empty_a[slot], ((ns / NSTAGE) - 1) & 1);
            mbar_expect_tx(full_a[slot], SBYTES);
            bulk_g2s(buf_a[slot], src + (size_t)ns * SBYTES, SBYTES, full_a[slot]);
        }
    }

    if (lane == 0) { s_m[w] = m; s_l[w] = l; }
    s_c[w][lane * 4 + 0] = ca.x;
    s_c[w][lane * 4 + 1] = ca.y;
    s_c[w][lane * 4 + 2] = ca.z;
    s_c[w][lane * 4 + 3] = ca.w;
    s_c[w][128 + lane * 4 + 0] = cb.x;
    s_c[w][128 + lane * 4 + 1] = cb.y;
    s_c[w][128 + lane * 4 + 2] = cb.z;
    s_c[w][128 + lane * 4 + 3] = cb.w;
    __syncthreads();

    float M = -1e30f;
#pragma unroll
    for (int ww = 0; ww < 8; ww++) M = fmaxf(M, s_m[ww]);
    float L = 0.f, C = 0.f;
#pragma unroll
    for (int ww = 0; ww < 8; ww++) {
        float e = __expf(s_m[ww] - M);
        L += s_l[ww] * e;
        C += s_c[ww][tid] * e;
    }
    const int pidx = b * NCH + chunk;
    g_pc[pidx * HH + tid] = C;
    if (tid == 0) { g_pm[pidx] = M; g_pl[pidx] = L; }
}

// ---------------------------------------------------------------------------
// Inline stats: M and invL for batch b from g_pm/g_pl (L2-hot, redundant).
// ---------------------------------------------------------------------------
__device__ __forceinline__ void batch_stats(int b, float& M, float& invL) {
    M = -1e30f;
#pragma unroll
    for (int i = 0; i < NCH; i++) M = fmaxf(M, g_pm[b * NCH + i]);
    float L = 0.f;
#pragma unroll
    for (int i = 0; i < NCH; i++)
        L += g_pl[b * NCH + i] * __expf(g_pm[b * NCH + i] - M);
    invL = 1.f / L;
}

// ---------------------------------------------------------------------------
// Kernel 2: attention_weights.  grid=(2, BB), block=256; 4 float4 per thread.
// ---------------------------------------------------------------------------
__global__ void __launch_bounds__(256) weights_kernel(float* __restrict__ out) {
    const int b = blockIdx.y;
    float M, invL;
    batch_stats(b, M, invL);

    const float4* sc4 = (const float4*)(g_scores + b * TT);
    float4* o4 = (float4*)(out + BB * HH + b * TT);
    const int base = blockIdx.x * 1024 + threadIdx.x;   // float4 index
#pragma unroll
    for (int k = 0; k < 4; k++) {
        const int t4 = base + k * 256;
        float4 sc = sc4[t4];
        float4 r;
        r.x = __expf(sc.x - M) * invL;
        r.y = __expf(sc.y - M) * invL;
        r.z = __expf(sc.z - M) * invL;
        r.w = __expf(sc.w - M) * invL;
        o4[t4] = r;
    }
}

// ---------------------------------------------------------------------------
// Kernel 3: tanh head.  grid=(8, BB), block=256 (8 warps).
// ---------------------------------------------------------------------------
__global__ void __launch_bounds__(256) head_kernel(const float* __restrict__ hs,
                                                   const float* __restrict__ W2,
                                                   float* __restrict__ out) {
    const int b = blockIdx.y;
    const int tid = threadIdx.x;
    const int w = tid >> 5;
    const int lane = tid & 31;

    float M, invL;
    batch_stats(b, M, invL);

    __shared__ float s_e[NCH];
    __shared__ __align__(16) float x[2 * HH];   // [ctx | ht]

    if (tid < NCH) s_e[tid] = __expf(g_pm[b * NCH + tid] - M);
    x[HH + tid] = hs[(size_t)b * TT * HH + (size_t)(TT - 1) * HH + tid];
    __syncthreads();

    const float* pc = g_pc + (size_t)b * NCH * HH + tid;
    float C0 = 0.f, C1 = 0.f, C2 = 0.f, C3 = 0.f;
#pragma unroll
    for (int i = 0; i < NCH; i += 4) {
        C0 += pc[(i + 0) * HH] * s_e[i + 0];
        C1 += pc[(i + 1) * HH] * s_e[i + 1];
        C2 += pc[(i + 2) * HH] * s_e[i + 2];
        C3 += pc[(i + 3) * HH] * s_e[i + 3];
    }
    x[tid] = (C0 + C1 + C2 + C3) * invL;
    __syncthreads();

    const float4* x4 = (const float4*)x;        // 128 float4

    const int o0 = blockIdx.x * 32 + w * 4;
    float acc0 = 0.f, acc1 = 0.f, acc2 = 0.f, acc3 = 0.f;
    const float4* r0 = (const float4*)(W2 + (size_t)(o0 + 0) * 2 * HH);
    const float4* r1 = (const float4*)(W2 + (size_t)(o0 + 1) * 2 * HH);
    const float4* r2 = (const float4*)(W2 + (size_t)(o0 + 2) * 2 * HH);
    const float4* r3 = (const float4*)(W2 + (size_t)(o0 + 3) * 2 * HH);
#pragma unroll
    for (int k = 0; k < 4; k++) {
        const int j = lane + 32 * k;            // coalesced within warp
        float4 xv = x4[j];
        float4 a0 = r0[j], a1 = r1[j], a2 = r2[j], a3 = r3[j];
        acc0 += a0.x * xv.x + a0.y * xv.y + a0.z * xv.z + a0.w * xv.w;
        acc1 += a1.x * xv.x + a1.y * xv.y + a1.z * xv.z + a1.w * xv.w;
        acc2 += a2.x * xv.x + a2.y * xv.y + a2.z * xv.z + a2.w * xv.w;
        acc3 += a3.x * xv.x + a3.y * xv.y + a3.z * xv.z + a3.w * xv.w;
    }
#pragma unroll
    for (int off = 16; off; off >>= 1) {
        acc0 += __shfl_xor_sync(0xffffffffu, acc0, off);
        acc1 += __shfl_xor_sync(0xffffffffu, acc1, off);
        acc2 += __shfl_xor_sync(0xffffffffu, acc2, off);
        acc3 += __shfl_xor_sync(0xffffffffu, acc3, off);
    }
    if (lane == 0) {
        out[b * HH + o0 + 0] = tanhf(acc0);
        out[b * HH + o0 + 1] = tanhf(acc1);
        out[b * HH + o0 + 2] = tanhf(acc2);
        out[b * HH + o0 + 3] = tanhf(acc3);
    }
}

// ---------------------------------------------------------------------------
extern "C" void kernel_launch(void* const* d_in, const int* in_sizes, int n_in,
                              void* d_out, int out_size) {
    const float* hs = (const float*)d_in[0];   // (32, 8192, 256) f32
    const float* W1 = (const float*)d_in[1];   // (256, 256) f32
    const float* W2 = (const float*)d_in[2];   // (256, 512) f32
    float* out = (float*)d_out;

    static int smem_set = 0;
    if (!smem_set) {
        cudaFuncSetAttribute(pass1_kernel,
                             cudaFuncAttributeMaxDynamicSharedMemorySize,
                             NSTAGE * SBYTES);
        smem_set = 1;
    }

    vpart_kernel<<<dim3(BB, 8), 256>>>(hs, W1);
    pass1_kernel<<<dim3(NCH, BB), 256, NSTAGE * SBYTES>>>(hs);
    weights_kernel<<<dim3(2, BB), 256>>>(out);
    head_kernel<<<dim3(8, BB), 256>>>(hs, W2, out);
}